// round 12
// baseline (speedup 1.0000x reference)
#include <cuda_runtime.h>
#include <math.h>

#define NC 64      // coarse samples
#define NF 128     // fine samples
#define NS 192     // combined
#define RPB 4      // rays per block (one warp each)
#define T (32 * RPB)
#define FULL 0xffffffffu

struct alignas(16) RayShm {
    float2 wc[NS];                 // (t, w) per combined sample   1536 B
    union {
        struct {
            float fine[NF];        // 512 B (sorted fine, post-sort)
            float cdf[NC + 2];     // 264 B (normalized CDF, [0]=0)
            float ct[NC];          // 256 B coarse t-vals
            float2 cdfp[NC];       // (cdf[i], cdf[i+1])  512 B, 8B aligned
            float2 ctp[NC];        // (ct[i],  ct[i+1])   512 B
        } a;
        float p[NS];               // 768 B overlay (clobbers fine+cdf after D)
    } u;
    float od[6];                   // origin xyz, dir xyz
    float pad[2];
};

// in-register compare-exchange
#define CEI(a, b, asc) { float lo_ = fminf(a, b), hi_ = fmaxf(a, b); \
                         a = (asc) ? lo_ : hi_; b = (asc) ? hi_ : lo_; }
// shuffle compare-exchange on all 4 regs, lane-distance d, direction up
#define CES(d, up) { bool km_ = (((l & (d)) == 0) == (up)); float pv_; \
    pv_ = __shfl_xor_sync(FULL, r0, (d)); r0 = km_ ? fminf(r0, pv_) : fmaxf(r0, pv_); \
    pv_ = __shfl_xor_sync(FULL, r1, (d)); r1 = km_ ? fminf(r1, pv_) : fmaxf(r1, pv_); \
    pv_ = __shfl_xor_sync(FULL, r2, (d)); r2 = km_ ? fminf(r2, pv_) : fmaxf(r2, pv_); \
    pv_ = __shfl_xor_sync(FULL, r3, (d)); r3 = km_ ? fminf(r3, pv_) : fmaxf(r3, pv_); }

__global__ void __launch_bounds__(T) nerf_kernel(
    const float* __restrict__ ro,   // [N,3]
    const float* __restrict__ rd,   // [N,3]
    const float* __restrict__ cw,   // [N,NC]
    const float* __restrict__ ct,   // [N,NC]
    const float* __restrict__ uu,   // [N,NF]
    const float* __restrict__ col,  // [N,NS,3]
    const float* __restrict__ dens, // [N,NS,1]
    float* __restrict__ out,        // rgb[3N] | depth[N] | opacity[N] | fine_points[N*NS*3]
    int N)
{
    __shared__ RayShm sh[RPB];
    const int warp = threadIdx.x >> 5;
    const int l    = threadIdx.x & 31;
    const int ray  = blockIdx.x * RPB + warp;
    if (ray >= N) return;
    RayShm& S = sh[warp];

    // ---- Phase A: origin/dir, coarse t (+pairs), weights -> CDF (+pairs) ----
    if (l < 3)      S.od[l] = ro[(size_t)ray * 3 + l];
    else if (l < 6) S.od[l] = rd[(size_t)ray * 3 + (l - 3)];

    {   // 2 elements per lane (2l, 2l+1), float2 coalesced
        float2 ctv = reinterpret_cast<const float2*>(ct + (size_t)ray * NC)[l];
        reinterpret_cast<float2*>(S.u.a.ct)[l] = ctv;
        float ctn = __shfl_down_sync(FULL, ctv.x, 1);      // ct[2l+2] (garbage l=31)
        if (l == 31) ctn = ctv.y;                          // safe filler (never read)
        S.u.a.ctp[2 * l]     = ctv;                        // (ct[2l],   ct[2l+1])
        S.u.a.ctp[2 * l + 1] = make_float2(ctv.y, ctn);    // (ct[2l+1], ct[2l+2])

        float2 cwp = reinterpret_cast<const float2*>(cw + (size_t)ray * NC)[l];
        float e0 = cwp.x + 1e-5f, e1 = cwp.y + 1e-5f;
        float pairv = e0 + e1;
        float scn = pairv;
        #pragma unroll
        for (int o = 1; o < 32; o <<= 1) {
            float t2 = __shfl_up_sync(FULL, scn, o);
            if (l >= o) scn += t2;
        }
        float total = __shfl_sync(FULL, scn, 31);
        float inv = __fdividef(1.0f, total);
        float c0 = (scn - pairv) * inv;          // cdf[2l]
        float c1 = (scn - pairv + e0) * inv;     // cdf[2l+1]
        float c2 = scn * inv;                    // cdf[2l+2]
        S.u.a.cdf[2 * l + 1] = c1;
        S.u.a.cdf[2 * l + 2] = c2;
        if (l == 0) S.u.a.cdf[0] = 0.f;
        S.u.a.cdfp[2 * l]     = make_float2(c0, c1);
        S.u.a.cdfp[2 * l + 1] = make_float2(c1, c2);
    }
    __syncwarp();

    // ---- Phase B: 4 inverse-CDF samples per lane (blocked 4l..4l+3) ----
    float r0, r1, r2, r3;
    {
        const float* a = S.u.a.cdf + 1;          // a[0..63] = cdf[1..64]
        // register-cached top 3 monobound levels (broadcast LDS, conflict-free)
        float c32v = a[31];
        float c16a = a[15], c16b = a[47];
        float c8a  = a[7],  c8b = a[23], c8c = a[39], c8d = a[55];
        float ct63 = S.u.a.ct[NC - 1];

        float4 u4 = *reinterpret_cast<const float4*>(uu + (size_t)ray * NF + 4 * l);
        float ua[4] = {u4.x, u4.y, u4.z, u4.w};
        float vv[4];
        #pragma unroll
        for (int m = 0; m < 4; m++) {
            float uj = ua[m];
            int base = 0;
            if (c32v <= uj) base = 32;                           // half=32
            float L2 = (base == 0) ? c16a : c16b;                // half=16
            if (L2 <= uj) base += 16;
            float L3 = (base < 32) ? ((base < 16) ? c8a  : c8b)
                                   : ((base < 48) ? c8c : c8d);  // half=8
            if (L3 <= uj) base += 8;
            if (a[base + 3] <= uj) base += 4;                    // half=4
            if (a[base + 1] <= uj) base += 2;                    // half=2
            if (a[base] <= uj) base += 1;                        // half=1
            if (a[base] <= uj) base += 1;                        // final, base <= 64
            // below = base, above = base+1 (both clamped to 63)
            if (base >= NC - 1) {
                vv[m] = ct63;          // tb == ta -> v = tb exactly (ref clamps)
            } else {
                float2 cc = S.u.a.cdfp[base];   // (cdf[base], cdf[base+1])
                float2 tt = S.u.a.ctp[base];    // (ct[base],  ct[base+1])
                float dn = cc.y - cc.x;
                if (dn < 1e-5f) dn = 1.f;
                vv[m] = tt.x + __fdividef(uj - cc.x, dn) * (tt.y - tt.x);
            }
        }
        r0 = vv[0]; r1 = vv[1]; r2 = vv[2]; r3 = vv[3];
    }

    // ---- Phase C: bitonic sort, 4 elems/lane blocked (elements 4l..4l+3) ----
    {
        // k=2
        CEI(r0, r1, true); CEI(r2, r3, false);
        // k=4
        { bool up = ((l & 1) == 0);
          CEI(r0, r2, up); CEI(r1, r3, up);
          CEI(r0, r1, up); CEI(r2, r3, up); }
        // k=8
        { bool up = ((l & 2) == 0);
          CES(1, up);
          CEI(r0, r2, up); CEI(r1, r3, up);
          CEI(r0, r1, up); CEI(r2, r3, up); }
        // k=16
        { bool up = ((l & 4) == 0);
          CES(2, up); CES(1, up);
          CEI(r0, r2, up); CEI(r1, r3, up);
          CEI(r0, r1, up); CEI(r2, r3, up); }
        // k=32
        { bool up = ((l & 8) == 0);
          CES(4, up); CES(2, up); CES(1, up);
          CEI(r0, r2, up); CEI(r1, r3, up);
          CEI(r0, r1, up); CEI(r2, r3, up); }
        // k=64
        { bool up = ((l & 16) == 0);
          CES(8, up); CES(4, up); CES(2, up); CES(1, up);
          CEI(r0, r2, up); CEI(r1, r3, up);
          CEI(r0, r1, up); CEI(r2, r3, up); }
        // k=128 (ascending)
        { CES(16, true); CES(8, true); CES(4, true); CES(2, true); CES(1, true);
          CEI(r0, r2, true); CEI(r1, r3, true);
          CEI(r0, r1, true); CEI(r2, r3, true); }
    }
    reinterpret_cast<float4*>(S.u.a.fine)[l] = make_float4(r0, r1, r2, r3);
    __syncwarp();

    // ---- Phase D: merge into wc[].x ----
    {   // fine elements: pos = (4l+m) + count{ coarse < v }  (monobound, len 64)
        // top 3 levels of ct register-cached (broadcast LDS)
        float g32 = S.u.a.ct[31];
        float g16a = S.u.a.ct[15], g16b = S.u.a.ct[47];
        float g8a = S.u.a.ct[7],  g8b = S.u.a.ct[23],
              g8c = S.u.a.ct[39], g8d = S.u.a.ct[55];
        float vv[4] = {r0, r1, r2, r3};
        #pragma unroll
        for (int m = 0; m < 4; m++) {
            float v = vv[m];
            int base = 0;
            if (g32 < v) base = 32;
            float L2 = (base == 0) ? g16a : g16b;
            if (L2 < v) base += 16;
            float L3 = (base < 32) ? ((base < 16) ? g8a : g8b)
                                   : ((base < 48) ? g8c : g8d);
            if (L3 < v) base += 8;
            if (S.u.a.ct[base + 3] < v) base += 4;
            if (S.u.a.ct[base + 1] < v) base += 2;
            if (S.u.a.ct[base] < v) base += 1;
            if (S.u.a.ct[base < NC - 1 ? base : NC - 1] < v && base < NC) base += 1;
            S.wc[4 * l + m + base].x = v;
        }
        // coarse elements: pos = idx + count{ fine <= c }  (len 128)
        // top 3 levels of sorted fine live in r3 across lanes -> shuffles
        float f64v = __shfl_sync(FULL, r3, 15);   // fine[63]
        float f32a = __shfl_sync(FULL, r3, 7);    // fine[31]
        float f32b = __shfl_sync(FULL, r3, 23);   // fine[95]
        float f16a = __shfl_sync(FULL, r3, 3);    // fine[15]
        float f16b = __shfl_sync(FULL, r3, 11);   // fine[47]
        float f16c = __shfl_sync(FULL, r3, 19);   // fine[79]
        float f16d = __shfl_sync(FULL, r3, 27);   // fine[111]
        #pragma unroll
        for (int m = 0; m < 2; m++) {
            int idx = l + 32 * m;
            float c = S.u.a.ct[idx];
            int base = 0;
            if (f64v <= c) base = 64;
            float L2 = (base == 0) ? f32a : f32b;
            if (L2 <= c) base += 32;
            float L3 = (base < 64) ? ((base < 32) ? f16a : f16b)
                                   : ((base < 96) ? f16c : f16d);
            if (L3 <= c) base += 16;
            if (S.u.a.fine[base + 7] <= c) base += 8;
            if (S.u.a.fine[base + 3] <= c) base += 4;
            if (S.u.a.fine[base + 1] <= c) base += 2;
            if (S.u.a.fine[base] <= c) base += 1;
            if (base < NF) { if (S.u.a.fine[base] <= c) base += 1; }
            S.wc[idx + base].x = c;
        }
    }
    __syncwarp();

    // ---- Phase E: p = exp(-d*dist)+1e-10, cyclic 6/lane, into p[] overlay ----
    float dx = S.od[3], dy = S.od[4], dz = S.od[5];
    float dnorm = sqrtf(dx * dx + dy * dy + dz * dz);
    {
        const float* db = dens + (size_t)ray * NS;
        #pragma unroll
        for (int m = 0; m < 6; m++) {
            int s = l + 32 * m;
            float tv = S.wc[s].x;
            float dist = (s < NS - 1) ? (S.wc[s + 1].x - tv) * dnorm : 1e10f * dnorm;
            float de = db[s];
            S.u.p[s] = __expf(-de * dist) + 1e-10f;
        }
    }
    __syncwarp();

    // ---- Phase F: transmittance scan (blocked 6/lane), weights -> wc[].y ----
    float ad = 0.f, ao = 0.f;
    {
        float q[6], al[6];
        #pragma unroll
        for (int m = 0; m < 6; m++) {
            float pp = S.u.p[6 * l + m];
            al[m] = 1.0f - pp;                    // alpha (to ~1e-10 abs)
            q[m] = (m == 0) ? pp : q[m - 1] * pp; // in-lane inclusive products
        }
        float scn = q[5];
        #pragma unroll
        for (int o = 1; o < 32; o <<= 1) {
            float t2 = __shfl_up_sync(FULL, scn, o);
            if (l >= o) scn *= t2;
        }
        float ex = __shfl_up_sync(FULL, scn, 1);
        float pref = (l == 0) ? 1.f : ex;
        #pragma unroll
        for (int m = 0; m < 6; m++) {
            float trans = (m == 0) ? pref : pref * q[m - 1];
            float w = al[m] * trans;
            int s = 6 * l + m;
            ad += w * S.wc[s].x;
            ao += w;
            S.wc[s].y = w;
        }
    }
    __syncwarp();

    // ---- Phase G: float4 fine_points store + color accumulation ----
    float ox = S.od[0], oy = S.od[1], oz = S.od[2];
    const float4* col4 = reinterpret_cast<const float4*>(col + (size_t)ray * (NS * 3));
    float4*       out4 = reinterpret_cast<float4*>(out + (size_t)5 * N + (size_t)ray * (NS * 3));
    float ar = 0.f, ag = 0.f, ab = 0.f;

    #pragma unroll
    for (int k = 0; k < 5; k++) {
        int i4 = l + 32 * k;
        if (k < 4 || i4 < (NS * 3) / 4) {        // 144 float4s; k<4 always valid
            int e  = i4 * 4;
            int s0 = e / 3;
            int c0 = e - 3 * s0;
            float2 wcA = S.wc[s0];
            float2 wcB = S.wc[s0 + 1];           // s0 max = 190 -> safe
            float4 cvv = col4[i4];
            float ce[4] = {cvv.x, cvv.y, cvv.z, cvv.w};
            float pe[4];
            #pragma unroll
            for (int j = 0; j < 4; j++) {
                int c = c0 + j;
                float2 wc = wcA;
                if (c >= 3) { c -= 3; wc = wcB; }
                float oc = (c == 0) ? ox : ((c == 1) ? oy : oz);
                float dc = (c == 0) ? dx : ((c == 1) ? dy : dz);
                pe[j] = fmaf(dc, wc.x, oc);
                float contrib = wc.y * ce[j];
                if (c == 0)      ar += contrib;
                else if (c == 1) ag += contrib;
                else             ab += contrib;
            }
            out4[i4] = make_float4(pe[0], pe[1], pe[2], pe[3]);
        }
    }

    // ---- warp reduction + outputs ----
    #pragma unroll
    for (int o = 16; o > 0; o >>= 1) {
        ar += __shfl_xor_sync(FULL, ar, o);
        ag += __shfl_xor_sync(FULL, ag, o);
        ab += __shfl_xor_sync(FULL, ab, o);
        ad += __shfl_xor_sync(FULL, ad, o);
        ao += __shfl_xor_sync(FULL, ao, o);
    }
    if (l == 0) {
        out[(size_t)ray * 3 + 0] = ar;
        out[(size_t)ray * 3 + 1] = ag;
        out[(size_t)ray * 3 + 2] = ab;
        out[(size_t)3 * N + ray] = ad;
        out[(size_t)4 * N + ray] = ao;
    }
}

extern "C" void kernel_launch(void* const* d_in, const int* in_sizes, int n_in,
                              void* d_out, int out_size)
{
    const float* ro  = (const float*)d_in[0];
    const float* rd  = (const float*)d_in[1];
    const float* cw  = (const float*)d_in[2];
    const float* ct  = (const float*)d_in[3];
    const float* uu  = (const float*)d_in[4];
    const float* col = (const float*)d_in[5];
    const float* de  = (const float*)d_in[6];
    int N = in_sizes[0] / 3;
    nerf_kernel<<<(N + RPB - 1) / RPB, T>>>(ro, rd, cw, ct, uu, col, de, (float*)d_out, N);
}

// round 15
// speedup vs baseline: 1.0456x; 1.0456x over previous
#include <cuda_runtime.h>
#include <math.h>

#define NC 64      // coarse samples
#define NF 128     // fine samples
#define NS 192     // combined
#define RPB 4      // rays per block (one warp each)
#define T (32 * RPB)
#define FULL 0xffffffffu

struct alignas(16) RayShm {
    float2 wc[NS];                 // (t, w) per combined sample   1536 B
    float fine[NF];                // sorted fine (post-sort)       512 B
    float cdf[NC + 2];             // normalized CDF, [0]=0         264 B
    float ct[NC];                  // coarse t-vals                 256 B
    float od[6];                   // origin xyz, dir xyz
    float pad[2];
};

// in-register compare-exchange
#define CEI(a, b, asc) { float lo_ = fminf(a, b), hi_ = fmaxf(a, b); \
                         a = (asc) ? lo_ : hi_; b = (asc) ? hi_ : lo_; }
// shuffle compare-exchange on all 4 regs, lane-distance d, direction up
#define CES(d, up) { bool km_ = (((l & (d)) == 0) == (up)); float pv_; \
    pv_ = __shfl_xor_sync(FULL, r0, (d)); r0 = km_ ? fminf(r0, pv_) : fmaxf(r0, pv_); \
    pv_ = __shfl_xor_sync(FULL, r1, (d)); r1 = km_ ? fminf(r1, pv_) : fmaxf(r1, pv_); \
    pv_ = __shfl_xor_sync(FULL, r2, (d)); r2 = km_ ? fminf(r2, pv_) : fmaxf(r2, pv_); \
    pv_ = __shfl_xor_sync(FULL, r3, (d)); r3 = km_ ? fminf(r3, pv_) : fmaxf(r3, pv_); }

__global__ void __launch_bounds__(T) nerf_kernel(
    const float* __restrict__ ro,   // [N,3]
    const float* __restrict__ rd,   // [N,3]
    const float* __restrict__ cw,   // [N,NC]
    const float* __restrict__ ct,   // [N,NC]
    const float* __restrict__ uu,   // [N,NF]
    const float* __restrict__ col,  // [N,NS,3]
    const float* __restrict__ dens, // [N,NS,1]
    float* __restrict__ out,        // rgb[3N] | depth[N] | opacity[N] | fine_points[N*NS*3]
    int N)
{
    __shared__ RayShm sh[RPB];
    const int warp = threadIdx.x >> 5;
    const int l    = threadIdx.x & 31;
    const int ray  = blockIdx.x * RPB + warp;
    if (ray >= N) return;
    RayShm& S = sh[warp];

    // ---- Phase A: origin/dir, coarse t, weights -> normalized CDF ----
    if (l < 3)      S.od[l] = ro[(size_t)ray * 3 + l];
    else if (l < 6) S.od[l] = rd[(size_t)ray * 3 + (l - 3)];

    {   // 2 elements per lane (2l, 2l+1), float2 coalesced
        float2 ctp = reinterpret_cast<const float2*>(ct + (size_t)ray * NC)[l];
        reinterpret_cast<float2*>(S.ct)[l] = ctp;
        float2 cwp = reinterpret_cast<const float2*>(cw + (size_t)ray * NC)[l];
        float e0 = cwp.x + 1e-5f, e1 = cwp.y + 1e-5f;
        float pairv = e0 + e1;
        float scn = pairv;
        #pragma unroll
        for (int o = 1; o < 32; o <<= 1) {
            float t2 = __shfl_up_sync(FULL, scn, o);
            if (l >= o) scn += t2;
        }
        float total = __shfl_sync(FULL, scn, 31);
        float inv = __fdividef(1.0f, total);
        float pre = scn - pairv;
        S.cdf[2 * l + 1] = (pre + e0) * inv;
        S.cdf[2 * l + 2] = scn * inv;
        if (l == 0) S.cdf[0] = 0.f;
    }
    __syncwarp();

    // ---- Phase B: 4 inverse-CDF samples per lane (blocked 4l..4l+3) ----
    float r0, r1, r2, r3;
    {
        const float* a = S.cdf + 1;              // a[0..63] = cdf[1..64]
        // register-cached top 3 monobound levels (broadcast LDS, conflict-free)
        float c32v = a[31];
        float c16a = a[15], c16b = a[47];
        float c8a  = a[7],  c8b = a[23], c8c = a[39], c8d = a[55];

        float4 u4 = *reinterpret_cast<const float4*>(uu + (size_t)ray * NF + 4 * l);
        float ua[4] = {u4.x, u4.y, u4.z, u4.w};
        float vv[4];
        #pragma unroll
        for (int m = 0; m < 4; m++) {
            float uj = ua[m];
            int base = 0;
            if (c32v <= uj) base = 32;                           // half=32
            float L2 = (base == 0) ? c16a : c16b;                // half=16
            if (L2 <= uj) base += 16;
            float L3 = (base < 32) ? ((base < 16) ? c8a : c8b)
                                   : ((base < 48) ? c8c : c8d);  // half=8
            if (L3 <= uj) base += 8;
            if (a[base + 3] <= uj) base += 4;                    // half=4
            if (a[base + 1] <= uj) base += 2;                    // half=2
            if (a[base] <= uj) base += 1;                        // half=1
            if (a[base] <= uj) base += 1;                        // final, base <= 64
            int lo = 1 + base;
            int below = (base < NC) ? base : (NC - 1);
            int above = (lo   < NC) ? lo   : (NC - 1);
            float cb = S.cdf[below], ca = S.cdf[above];
            float tb = S.ct[below],  ta = S.ct[above];
            float dn = ca - cb;
            if (dn < 1e-5f) dn = 1.f;
            vv[m] = tb + __fdividef(uj - cb, dn) * (ta - tb);
        }
        r0 = vv[0]; r1 = vv[1]; r2 = vv[2]; r3 = vv[3];
    }

    // ---- Phase C: bitonic sort, 4 elems/lane blocked (elements 4l..4l+3) ----
    {
        // k=2
        CEI(r0, r1, true); CEI(r2, r3, false);
        // k=4
        { bool up = ((l & 1) == 0);
          CEI(r0, r2, up); CEI(r1, r3, up);
          CEI(r0, r1, up); CEI(r2, r3, up); }
        // k=8
        { bool up = ((l & 2) == 0);
          CES(1, up);
          CEI(r0, r2, up); CEI(r1, r3, up);
          CEI(r0, r1, up); CEI(r2, r3, up); }
        // k=16
        { bool up = ((l & 4) == 0);
          CES(2, up); CES(1, up);
          CEI(r0, r2, up); CEI(r1, r3, up);
          CEI(r0, r1, up); CEI(r2, r3, up); }
        // k=32
        { bool up = ((l & 8) == 0);
          CES(4, up); CES(2, up); CES(1, up);
          CEI(r0, r2, up); CEI(r1, r3, up);
          CEI(r0, r1, up); CEI(r2, r3, up); }
        // k=64
        { bool up = ((l & 16) == 0);
          CES(8, up); CES(4, up); CES(2, up); CES(1, up);
          CEI(r0, r2, up); CEI(r1, r3, up);
          CEI(r0, r1, up); CEI(r2, r3, up); }
        // k=128 (ascending)
        { CES(16, true); CES(8, true); CES(4, true); CES(2, true); CES(1, true);
          CEI(r0, r2, true); CEI(r1, r3, true);
          CEI(r0, r1, true); CEI(r2, r3, true); }
    }
    reinterpret_cast<float4*>(S.fine)[l] = make_float4(r0, r1, r2, r3);
    __syncwarp();

    // ---- Phase D: merge into wc[].x ----
    {   // fine elements: pos = (4l+m) + count{ coarse < v }  (monobound, len 64)
        float vv[4] = {r0, r1, r2, r3};
        #pragma unroll
        for (int m = 0; m < 4; m++) {
            float v = vv[m];
            int base = 0;
            #pragma unroll
            for (int half = 32; half >= 1; half >>= 1)
                if (S.ct[base + half - 1] < v) base += half;      // base <= 63
            if (base < NC) { if (S.ct[base] < v) base += 1; }
            S.wc[4 * l + m + base].x = v;
        }
        // coarse elements: pos = idx + count{ fine <= c }  (len 128)
        #pragma unroll
        for (int m = 0; m < 2; m++) {
            int idx = l + 32 * m;
            float c = S.ct[idx];
            int base = 0;
            #pragma unroll
            for (int half = 64; half >= 1; half >>= 1)
                if (S.fine[base + half - 1] <= c) base += half;   // base <= 127
            if (base < NF) { if (S.fine[base] <= c) base += 1; }
            S.wc[idx + base].x = c;
        }
    }
    __syncwarp();

    // ---- Phase E+F fused: blocked 6 samples/lane, register-resident ----
    float dx = S.od[3], dy = S.od[4], dz = S.od[5];
    float dnorm = sqrtf(dx * dx + dy * dy + dz * dz);
    float ad = 0.f, ao = 0.f;
    {
        float4* wc4 = reinterpret_cast<float4*>(S.wc);    // 16B aligned (48l%16==0)
        float4 ta4 = wc4[3 * l], tb4 = wc4[3 * l + 1], tc4 = wc4[3 * l + 2];
        float t[6] = {ta4.x, ta4.z, tb4.x, tb4.z, tc4.x, tc4.z};
        float tn = __shfl_down_sync(FULL, t[0], 1);       // t[6l+6] (garbage l=31, unused)

        const float2* db2 = reinterpret_cast<const float2*>(dens + (size_t)ray * NS) + 3 * l;
        float2 d0 = db2[0], d1 = db2[1], d2 = db2[2];
        float de[6] = {d0.x, d0.y, d1.x, d1.y, d2.x, d2.y};

        float p[6], q[6];
        #pragma unroll
        for (int m = 0; m < 6; m++) {
            float nxt = (m < 5) ? t[m + 1] : tn;
            float dist = (6 * l + m < NS - 1) ? (nxt - t[m]) * dnorm : 1e10f * dnorm;
            p[m] = __expf(-de[m] * dist) + 1e-10f;
            q[m] = (m == 0) ? p[m] : q[m - 1] * p[m];
        }
        float scn = q[5];
        #pragma unroll
        for (int o = 1; o < 32; o <<= 1) {
            float t2 = __shfl_up_sync(FULL, scn, o);
            if (l >= o) scn *= t2;
        }
        float ex = __shfl_up_sync(FULL, scn, 1);
        float pref = (l == 0) ? 1.f : ex;

        float w[6];
        #pragma unroll
        for (int m = 0; m < 6; m++) {
            float trans = (m == 0) ? pref : pref * q[m - 1];
            w[m] = (1.0f - p[m]) * trans;         // alpha - 1e-10, as before
            ad += w[m] * t[m];
            ao += w[m];
        }
        wc4[3 * l]     = make_float4(t[0], w[0], t[1], w[1]);
        wc4[3 * l + 1] = make_float4(t[2], w[2], t[3], w[3]);
        wc4[3 * l + 2] = make_float4(t[4], w[4], t[5], w[5]);
    }
    __syncwarp();

    // ---- Phase G: float4 fine_points store + color accumulation ----
    float ox = S.od[0], oy = S.od[1], oz = S.od[2];
    const float4* col4 = reinterpret_cast<const float4*>(col + (size_t)ray * (NS * 3));
    float4*       out4 = reinterpret_cast<float4*>(out + (size_t)5 * N + (size_t)ray * (NS * 3));
    float ar = 0.f, ag = 0.f, ab = 0.f;

    #pragma unroll
    for (int k = 0; k < 5; k++) {
        int i4 = l + 32 * k;
        if (k < 4 || i4 < (NS * 3) / 4) {        // 144 float4s; k<4 always valid
            int e  = i4 * 4;
            int s0 = e / 3;
            int c0 = e - 3 * s0;
            float2 wcA = S.wc[s0];
            float2 wcB = S.wc[s0 + 1];           // s0 max = 190 -> safe
            float4 cvv = col4[i4];
            float ce[4] = {cvv.x, cvv.y, cvv.z, cvv.w};
            float pe[4];
            #pragma unroll
            for (int j = 0; j < 4; j++) {
                int c = c0 + j;
                float2 wc = wcA;
                if (c >= 3) { c -= 3; wc = wcB; }
                float oc = (c == 0) ? ox : ((c == 1) ? oy : oz);
                float dc = (c == 0) ? dx : ((c == 1) ? dy : dz);
                pe[j] = fmaf(dc, wc.x, oc);
                float contrib = wc.y * ce[j];
                if (c == 0)      ar += contrib;
                else if (c == 1) ag += contrib;
                else             ab += contrib;
            }
            out4[i4] = make_float4(pe[0], pe[1], pe[2], pe[3]);
        }
    }

    // ---- warp reduction + outputs ----
    #pragma unroll
    for (int o = 16; o > 0; o >>= 1) {
        ar += __shfl_xor_sync(FULL, ar, o);
        ag += __shfl_xor_sync(FULL, ag, o);
        ab += __shfl_xor_sync(FULL, ab, o);
        ad += __shfl_xor_sync(FULL, ad, o);
        ao += __shfl_xor_sync(FULL, ao, o);
    }
    if (l == 0) {
        out[(size_t)ray * 3 + 0] = ar;
        out[(size_t)ray * 3 + 1] = ag;
        out[(size_t)ray * 3 + 2] = ab;
        out[(size_t)3 * N + ray] = ad;
        out[(size_t)4 * N + ray] = ao;
    }
}

extern "C" void kernel_launch(void* const* d_in, const int* in_sizes, int n_in,
                              void* d_out, int out_size)
{
    const float* ro  = (const float*)d_in[0];
    const float* rd  = (const float*)d_in[1];
    const float* cw  = (const float*)d_in[2];
    const float* ct  = (const float*)d_in[3];
    const float* uu  = (const float*)d_in[4];
    const float* col = (const float*)d_in[5];
    const float* de  = (const float*)d_in[6];
    int N = in_sizes[0] / 3;
    nerf_kernel<<<(N + RPB - 1) / RPB, T>>>(ro, rd, cw, ct, uu, col, de, (float*)d_out, N);
}